// round 13
// baseline (speedup 1.0000x reference)
#include <cuda_runtime.h>
#include <cuda_bf16.h>
#include <cstdint>
#include <math.h>

// Problem constants: B=2, H=16, S=2048, D=64
#define SQ 2048
#define DD 64
#define NBH 32
#define SCALE 0.125f
#define CH 128           // k-chunk columns
#define QT 128           // q rows per block (8 warps x 16 rows)

#define KPST 36          // Khi/Klo row stride in uint32 (32 + 4 pad)
#define VST2 72          // V row stride in floats (64 + 8 pad) — untransposed
#define PST  72          // P float stride (half-chunk: 64 cols + pad)

// smem byte offsets
#define SM_KHI 0
#define SM_KLO (SM_KHI + 128*KPST*4)            // 18432
#define SM_V   (SM_KLO + 128*KPST*4)            // 36864   (2 buffers)
#define VBUF_B (128*VST2*4)                     // 36864 per buffer
#define SM_P   (SM_V + 2*VBUF_B)                // 110592
#define SMEM_BYTES (SM_P + 128*PST*4)           // 147456

__device__ __forceinline__ uint32_t smem_u32(const void* p) {
    uint32_t a;
    asm("{ .reg .u64 t; cvta.to.shared.u64 t, %1; cvt.u32.u64 %0, t; }"
        : "=r"(a) : "l"(p));
    return a;
}
#define CP_ASYNC16(dst_u32, src_ptr) \
    asm volatile("cp.async.cg.shared.global [%0], [%1], 16;" \
                 :: "r"(dst_u32), "l"(src_ptr) : "memory")
#define CP_COMMIT() asm volatile("cp.async.commit_group;" ::: "memory")
#define CP_WAIT(n)  asm volatile("cp.async.wait_group %0;" :: "n"(n) : "memory")

__device__ __forceinline__ float to_tf32(float x) {
    float r; asm("cvt.rna.tf32.f32 %0, %1;" : "=f"(r) : "f"(x)); return r;
}

// tf32 m16n8k8 (PV). HW truncates fp32 operands to tf32.
__device__ __forceinline__ void mma8(float c[4],
                                     float a0, float a1, float a2, float a3,
                                     float b0, float b1) {
    asm volatile(
        "mma.sync.aligned.m16n8k8.row.col.f32.tf32.tf32.f32 "
        "{%0,%1,%2,%3}, {%4,%5,%6,%7}, {%8,%9}, {%0,%1,%2,%3};"
        : "+f"(c[0]), "+f"(c[1]), "+f"(c[2]), "+f"(c[3])
        : "r"(__float_as_uint(a0)), "r"(__float_as_uint(a1)),
          "r"(__float_as_uint(a2)), "r"(__float_as_uint(a3)),
          "r"(__float_as_uint(b0)), "r"(__float_as_uint(b1)));
}

// bf16 m16n8k16 (QK)
__device__ __forceinline__ void mma16bf(float c[4], const uint32_t a[4],
                                        uint32_t b0, uint32_t b1) {
    asm volatile(
        "mma.sync.aligned.m16n8k16.row.col.f32.bf16.bf16.f32 "
        "{%0,%1,%2,%3}, {%4,%5,%6,%7}, {%8,%9}, {%0,%1,%2,%3};"
        : "+f"(c[0]), "+f"(c[1]), "+f"(c[2]), "+f"(c[3])
        : "r"(a[0]), "r"(a[1]), "r"(a[2]), "r"(a[3]), "r"(b0), "r"(b1));
}

// pack two floats' bf16 hi-parts and residual lo-parts
__device__ __forceinline__ void bf_split2(float x0, float x1,
                                          uint32_t& hp, uint32_t& lp) {
    __nv_bfloat16 h0 = __float2bfloat16(x0);
    __nv_bfloat16 h1 = __float2bfloat16(x1);
    float l0 = x0 - __bfloat162float(h0);
    float l1 = x1 - __bfloat162float(h1);
    hp = ((uint32_t)__bfloat16_as_ushort(h1) << 16) | __bfloat16_as_ushort(h0);
    lp = ((uint32_t)__bfloat16_as_ushort(__float2bfloat16(l1)) << 16)
       | __bfloat16_as_ushort(__float2bfloat16(l0));
}

__global__ __launch_bounds__(256, 1)
void attn_fwd_kernel(const float* __restrict__ Qg, const float* __restrict__ Kg,
                     const float* __restrict__ Vg, float* __restrict__ Og,
                     float* __restrict__ Wg)
{
    extern __shared__ unsigned char smb[];
    uint32_t* Khi = (uint32_t*)(smb + SM_KHI);
    uint32_t* Klo = (uint32_t*)(smb + SM_KLO);
    float*    Vsm = (float*)(smb + SM_V);       // 2 buffers of [128][VST2]
    float*    Ps  = (float*)(smb + SM_P);

    const int tid  = threadIdx.x;
    const int wid  = tid >> 5;
    const int lane = tid & 31;
    const int g    = lane >> 2;     // 0..7
    const int t    = lane & 3;      // 0..3

    const int qt = 15 - (int)blockIdx.x;  // heavy tiles first
    const int bh = blockIdx.y;
    const int q0 = qt * QT;
    const int nch = qt + 1;
    const size_t base = (size_t)bh * SQ * DD;

    const int row0 = wid * 16 + g;
    const int row1 = row0 + 8;
    const int qg0  = q0 + row0;
    const int qg1  = q0 + row1;

    // staging decode
    const int sK_dg = tid & 7, sK_r = tid >> 3;            // K: 32 rows/iter
    const int sV_key = tid >> 4, sV_d = (tid & 15) << 2;   // V: 16 keys/iter
    const uint32_t vbase_u32 = smem_u32(Vsm);
    const uint32_t vdst_off  = (uint32_t)(sV_key * VST2 + sV_d) * 4;

    // ---- cp.async V chunk 0 into buffer 0 ----
    {
        const float* vp = Vg + base + (size_t)sV_key * DD + sV_d;
        #pragma unroll
        for (int it = 0; it < 8; it++)
            CP_ASYNC16(vbase_u32 + vdst_off + (uint32_t)(it * 16 * VST2 * 4),
                       vp + (size_t)(it * 16) * DD);
        CP_COMMIT();
    }

    // ---- prefetch K chunk 0 into registers (bf16 split) ----
    uint4 pkh[4], pkl[4];
    {
        const float* kp = Kg + base + (size_t)sK_r * DD + sK_dg * 8;
        #pragma unroll
        for (int it = 0; it < 4; it++) {
            float4 k0 = *(const float4*)(kp + (size_t)(it * 32) * DD);
            float4 k1 = *(const float4*)(kp + (size_t)(it * 32) * DD + 4);
            bf_split2(k0.x, k0.y, pkh[it].x, pkl[it].x);
            bf_split2(k0.z, k0.w, pkh[it].y, pkl[it].y);
            bf_split2(k1.x, k1.y, pkh[it].z, pkl[it].z);
            bf_split2(k1.z, k1.w, pkh[it].w, pkl[it].w);
        }
    }

    // ---- stage raw Q into P area, build bf16 hi/lo A-frags (persist) ----
    for (int i4 = tid; i4 < QT * DD / 4; i4 += 256) {
        int r = i4 >> 4, c = (i4 & 15) << 2;
        float4 v = *(const float4*)(Qg + base + (size_t)(q0 + r) * DD + c);
        *(float4*)&Ps[r * PST + c] = v;
    }
    __syncthreads();

    uint32_t qh[4][4], ql[4][4];
    #pragma unroll
    for (int k16 = 0; k16 < 4; k16++) {
        float2 qa = *(const float2*)&Ps[row0 * PST + k16 * 16 + 2 * t];
        float2 qb = *(const float2*)&Ps[row1 * PST + k16 * 16 + 2 * t];
        float2 qc = *(const float2*)&Ps[row0 * PST + k16 * 16 + 2 * t + 8];
        float2 qd = *(const float2*)&Ps[row1 * PST + k16 * 16 + 2 * t + 8];
        bf_split2(qa.x, qa.y, qh[k16][0], ql[k16][0]);
        bf_split2(qb.x, qb.y, qh[k16][1], ql[k16][1]);
        bf_split2(qc.x, qc.y, qh[k16][2], ql[k16][2]);
        bf_split2(qd.x, qd.y, qh[k16][3], ql[k16][3]);
    }

    float o[8][4];
    #pragma unroll
    for (int n = 0; n < 8; n++)
        #pragma unroll
        for (int j = 0; j < 4; j++) o[n][j] = 0.f;
    float psum0 = 0.f, psum1 = 0.f;

    // ================= pass 1: flash (O + rowsums; no W traffic) =============
    for (int ch = 0; ch < nch; ch++) {
        const int kb = ch * CH;
        float* Vb = Vsm + (ch & 1) * (VBUF_B / 4);
        __syncthreads();   // previous chunk compute done

        // ---- STS prefetched K (bf16 hi/lo) ----
        {
            const int pos0 = sK_r * KPST + (sK_dg >> 1) * 8 + (sK_dg & 1) * 4;
            #pragma unroll
            for (int it = 0; it < 4; it++) {
                *(uint4*)&Khi[pos0 + it * 32 * KPST] = pkh[it];
                *(uint4*)&Klo[pos0 + it * 32 * KPST] = pkl[it];
            }
        }
        // ---- cp.async next V chunk into the other buffer ----
        if (ch + 1 < nch) {
            const uint32_t dst = vbase_u32 + (uint32_t)(((ch + 1) & 1) * VBUF_B)
                               + vdst_off;
            const float* vp = Vg + base + (size_t)(kb + CH + sV_key) * DD + sV_d;
            #pragma unroll
            for (int it = 0; it < 8; it++)
                CP_ASYNC16(dst + (uint32_t)(it * 16 * VST2 * 4),
                           vp + (size_t)(it * 16) * DD);
            CP_COMMIT();
            CP_WAIT(1);    // this chunk's V group arrived
        } else {
            CP_WAIT(0);
        }
        __syncthreads();   // K STS + V arrivals visible

        // ---- round this chunk's V to tf32 in place (restores accuracy) ----
        {
            float* vq = Vb + sV_key * VST2 + sV_d;
            #pragma unroll
            for (int it = 0; it < 8; it++) {
                float4 v = *(const float4*)(vq + it * 16 * VST2);
                v.x = to_tf32(v.x); v.y = to_tf32(v.y);
                v.z = to_tf32(v.z); v.w = to_tf32(v.w);
                *(float4*)(vq + it * 16 * VST2) = v;
            }
        }
        __syncthreads();

        const bool diag = (ch == qt);

        #pragma unroll
        for (int h = 0; h < 2; h++) {
            // ---- S half: 3x bf16 MMA (hh + lh + hl) ----
            float s[8][4];
            #pragma unroll
            for (int n = 0; n < 8; n++)
                #pragma unroll
                for (int j = 0; j < 4; j++) s[n][j] = 0.f;

            #pragma unroll
            for (int k16 = 0; k16 < 4; k16++) {
                #pragma unroll
                for (int nt = 0; nt < 8; nt++) {
                    const int krow = (h * 64 + nt * 8 + g) * KPST + k16 * 8 + t;
                    uint32_t b0h = Khi[krow], b1h = Khi[krow + 4];
                    uint32_t b0l = Klo[krow], b1l = Klo[krow + 4];
                    mma16bf(s[nt], qh[k16], b0h, b1h);
                    mma16bf(s[nt], ql[k16], b0h, b1h);
                    mma16bf(s[nt], qh[k16], b0l, b1l);
                }
            }

            // ---- prefetch next K (after QK so LDGs don't delay QK LDS) ----
            if (h == 0 && ch + 1 < nch) {
                const float* kp = Kg + base + (size_t)(kb + CH + sK_r) * DD
                                + sK_dg * 8;
                #pragma unroll
                for (int it = 0; it < 4; it++) {
                    float4 k0 = *(const float4*)(kp + (size_t)(it * 32) * DD);
                    float4 k1 = *(const float4*)(kp + (size_t)(it * 32) * DD + 4);
                    bf_split2(k0.x, k0.y, pkh[it].x, pkl[it].x);
                    bf_split2(k0.z, k0.w, pkh[it].y, pkl[it].y);
                    bf_split2(k1.x, k1.y, pkh[it].z, pkl[it].z);
                    bf_split2(k1.z, k1.w, pkh[it].w, pkl[it].w);
                }
            }

            // ---- exp, mask, psum, P -> smem (raw fp32) ----
            #pragma unroll
            for (int nt = 0; nt < 8; nt++) {
                const int col = kb + h * 64 + nt * 8 + 2 * t;
                float p00 = __expf(s[nt][0] * SCALE);
                float p01 = __expf(s[nt][1] * SCALE);
                float p10 = __expf(s[nt][2] * SCALE);
                float p11 = __expf(s[nt][3] * SCALE);
                if (diag) {
                    if (col     > qg0) p00 = 0.f;
                    if (col + 1 > qg0) p01 = 0.f;
                    if (col     > qg1) p10 = 0.f;
                    if (col + 1 > qg1) p11 = 0.f;
                }
                psum0 += p00 + p01;
                psum1 += p10 + p11;
                *(float2*)&Ps[row0 * PST + nt * 8 + 2 * t] = make_float2(p00, p01);
                *(float2*)&Ps[row1 * PST + nt * 8 + 2 * t] = make_float2(p10, p11);
            }
            __syncwarp();   // P rows are warp-private

            // ---- O += P_half @ V_half (tf32; P rounds to same as trunc>=0) ----
            #pragma unroll
            for (int k = 0; k < 8; k++) {
                float a0 = Ps[row0 * PST + 8 * k + t];
                float a1 = Ps[row1 * PST + 8 * k + t];
                float a2 = Ps[row0 * PST + 8 * k + t + 4];
                float a3 = Ps[row1 * PST + 8 * k + t + 4];
                const float* vr0 = Vb + (h * 64 + 8 * k + t) * VST2;
                const float* vr1 = vr0 + 4 * VST2;
                #pragma unroll
                for (int nt = 0; nt < 8; nt++) {
                    const int d = nt * 8 + g;
                    mma8(o[nt], a0, a1, a2, a3, vr0[d], vr1[d]);
                }
            }
            __syncwarp();   // Ps reused by next half
        }
    }

    // ---- rowsum reduce across the 4 quad lanes -> 1/l ----
    psum0 += __shfl_xor_sync(0xffffffffu, psum0, 1);
    psum0 += __shfl_xor_sync(0xffffffffu, psum0, 2);
    psum1 += __shfl_xor_sync(0xffffffffu, psum1, 1);
    psum1 += __shfl_xor_sync(0xffffffffu, psum1, 2);
    const float inv0 = 1.0f / psum0;
    const float inv1 = 1.0f / psum1;

    // ---- re-prime K chunk 0 prefetch for pass 2 (L2-hot) ----
    if (Wg) {
        const float* kp = Kg + base + (size_t)sK_r * DD + sK_dg * 8;
        #pragma unroll
        for (int it = 0; it < 4; it++) {
            float4 k0 = *(const float4*)(kp + (size_t)(it * 32) * DD);
            float4 k1 = *(const float4*)(kp + (size_t)(it * 32) * DD + 4);
            bf_split2(k0.x, k0.y, pkh[it].x, pkl[it].x);
            bf_split2(k0.z, k0.w, pkh[it].y, pkl[it].y);
            bf_split2(k1.x, k1.y, pkh[it].z, pkl[it].z);
            bf_split2(k1.z, k1.w, pkh[it].w, pkl[it].w);
        }
    }

    // ---- O = acc * inv -> global ----
    #pragma unroll
    for (int nt = 0; nt < 8; nt++) {
        const int col = nt * 8 + 2 * t;
        *(float2*)(Og + base + (size_t)qg0 * DD + col) =
            make_float2(o[nt][0] * inv0, o[nt][1] * inv0);
        *(float2*)(Og + base + (size_t)qg1 * DD + col) =
            make_float2(o[nt][2] * inv1, o[nt][3] * inv1);
    }

    // ============ pass 2: recompute S, write NORMALIZED W once ==============
    if (Wg) {
        for (int ch = 0; ch < nch; ch++) {
            const int kb = ch * CH;
            __syncthreads();   // previous chunk's QK reads done; K smem free

            {   // STS prefetched K
                const int pos0 = sK_r * KPST + (sK_dg >> 1) * 8 + (sK_dg & 1) * 4;
                #pragma unroll
                for (int it = 0; it < 4; it++) {
                    *(uint4*)&Khi[pos0 + it * 32 * KPST] = pkh[it];
                    *(uint4*)&Klo[pos0 + it * 32 * KPST] = pkl[it];
                }
            }
            __syncthreads();

            const bool diag = (ch == qt);

            #pragma unroll
            for (int h = 0; h < 2; h++) {
                float s[8][4];
                #pragma unroll
                for (int n = 0; n < 8; n++)
                    #pragma unroll
                    for (int j = 0; j < 4; j++) s[n][j] = 0.f;

                #pragma unroll
                for (int k16 = 0; k16 < 4; k16++) {
                    #pragma unroll
                    for (int nt = 0; nt < 8; nt++) {
                        const int krow = (h * 64 + nt * 8 + g) * KPST + k16 * 8 + t;
                        uint32_t b0h = Khi[krow], b1h = Khi[krow + 4];
                        uint32_t b0l = Klo[krow], b1l = Klo[krow + 4];
                        mma16bf(s[nt], qh[k16], b0h, b1h);
                        mma16bf(s[nt], ql[k16], b0h, b1h);
                        mma16bf(s[nt], qh[k16], b0l, b1l);
                    }
                }

                if (h == 0 && ch + 1 < nch) {   // prefetch next K (L2-hot)
                    const float* kp = Kg + base + (size_t)(kb + CH + sK_r) * DD
                                    + sK_dg * 8;
                    #pragma unroll
                    for (int it = 0; it < 4; it++) {
                        float4 k0 = *(const float4*)(kp + (size_t)(it * 32) * DD);
                        float4 k1 = *(const float4*)(kp + (size_t)(it * 32) * DD + 4);
                        bf_split2(k0.x, k0.y, pkh[it].x, pkl[it].x);
                        bf_split2(k0.z, k0.w, pkh[it].y, pkl[it].y);
                        bf_split2(k1.x, k1.y, pkh[it].z, pkl[it].z);
                        bf_split2(k1.z, k1.w, pkh[it].w, pkl[it].w);
                    }
                }

                // normalized weights into Ps
                #pragma unroll
                for (int nt = 0; nt < 8; nt++) {
                    const int col = kb + h * 64 + nt * 8 + 2 * t;
                    float p00 = __expf(s[nt][0] * SCALE) * inv0;
                    float p01 = __expf(s[nt][1] * SCALE) * inv0;
                    float p10 = __expf(s[nt][2] * SCALE) * inv1;
                    float p11 = __expf(s[nt][3] * SCALE) * inv1;
                    if (diag) {
                        if (col     > qg0) p00 = 0.f;
                        if (col + 1 > qg0) p01 = 0.f;
                        if (col     > qg1) p10 = 0.f;
                        if (col + 1 > qg1) p11 = 0.f;
                    }
                    *(float2*)&Ps[row0 * PST + nt * 8 + 2 * t] = make_float2(p00, p01);
                    *(float2*)&Ps[row1 * PST + nt * 8 + 2 * t] = make_float2(p10, p11);
                }
                __syncwarp();

                // coalesced STG.128 of this warp's 16 rows
                {
                    const int wr2 = lane >> 4;       // 0/1
                    const int c4  = (lane & 15) << 2;
                    float* wb = Wg + ((size_t)bh * SQ + q0) * SQ + kb + h * 64 + c4;
                    #pragma unroll
                    for (int st = 0; st < 8; st++) {
                        const int r = wid * 16 + st * 2 + wr2;
                        float4 v = *(const float4*)&Ps[r * PST + c4];
                        *(float4*)(wb + (size_t)r * SQ) = v;
                    }
                }
                __syncwarp();
            }
        }

        // ---- zero-fill cols [q0+128, SQ) of this block's 128 rows ----
        const int z0 = q0 + QT;
        const int zn4 = (SQ - z0) >> 2;
        if (zn4 > 0) {
            const float4 z = make_float4(0.f, 0.f, 0.f, 0.f);
            for (int r = wid; r < QT; r += 8) {
                float4* wp = (float4*)(Wg + ((size_t)bh * SQ + q0 + r) * SQ + z0);
                for (int c = lane; c < zn4; c += 32) wp[c] = z;
            }
        }
    }
}

extern "C" void kernel_launch(void* const* d_in, const int* in_sizes, int n_in,
                              void* d_out, int out_size)
{
    const float* Q = (const float*)d_in[0];
    const float* K = (const float*)d_in[1];
    const float* V = (const float*)d_in[2];
    // d_in[3]: causal mask — implemented analytically.

    float* out = (float*)d_out;
    const long long outN = (long long)NBH * SQ * DD;          //   4,194,304
    const long long wN   = (long long)NBH * SQ * SQ;          // 134,217,728
    float* W = ((long long)out_size >= outN + wN) ? (out + outN) : (float*)0;

    cudaFuncSetAttribute(attn_fwd_kernel,
                         cudaFuncAttributeMaxDynamicSharedMemorySize, SMEM_BYTES);

    dim3 grid(SQ / QT, NBH);
    attn_fwd_kernel<<<grid, 256, SMEM_BYTES>>>(Q, K, V, out, W);
}

// round 14
// speedup vs baseline: 1.0587x; 1.0587x over previous
#include <cuda_runtime.h>
#include <cuda_bf16.h>
#include <cstdint>
#include <math.h>

// Problem constants: B=2, H=16, S=2048, D=64
#define SQ 2048
#define DD 64
#define NBH 32
#define SCALE 0.125f
#define CH 128           // k-chunk columns
#define QT 128           // q rows per block (8 warps x 16 rows)

#define KIST 36          // K interleaved row stride in uint2 ({hi,lo} pairs)
#define VST2 72          // V row stride in floats (64 + 8 pad) — untransposed
#define PST  72          // P float stride (half-chunk: 64 cols + pad)

// smem byte offsets
#define SM_KIV 0                                // 128*36*8 = 36864
#define SM_V   (SM_KIV + 128*KIST*8)            // 36864   (2 buffers)
#define VBUF_B (128*VST2*4)                     // 36864 per buffer
#define SM_P   (SM_V + 2*VBUF_B)                // 110592
#define SMEM_BYTES (SM_P + 128*PST*4)           // 147456

__device__ float g_Linv[NBH * SQ];

__device__ __forceinline__ uint32_t smem_u32(const void* p) {
    uint32_t a;
    asm("{ .reg .u64 t; cvta.to.shared.u64 t, %1; cvt.u32.u64 %0, t; }"
        : "=r"(a) : "l"(p));
    return a;
}
#define CP_ASYNC16(dst_u32, src_ptr) \
    asm volatile("cp.async.cg.shared.global [%0], [%1], 16;" \
                 :: "r"(dst_u32), "l"(src_ptr) : "memory")
#define CP_COMMIT() asm volatile("cp.async.commit_group;" ::: "memory")
#define CP_WAIT(n)  asm volatile("cp.async.wait_group %0;" :: "n"(n) : "memory")

__device__ __forceinline__ float to_tf32(float x) {
    float r; asm("cvt.rna.tf32.f32 %0, %1;" : "=f"(r) : "f"(x)); return r;
}

// tf32 m16n8k8 (PV). HW truncates fp32 operands to tf32.
__device__ __forceinline__ void mma8(float c[4],
                                     float a0, float a1, float a2, float a3,
                                     float b0, float b1) {
    asm volatile(
        "mma.sync.aligned.m16n8k8.row.col.f32.tf32.tf32.f32 "
        "{%0,%1,%2,%3}, {%4,%5,%6,%7}, {%8,%9}, {%0,%1,%2,%3};"
        : "+f"(c[0]), "+f"(c[1]), "+f"(c[2]), "+f"(c[3])
        : "r"(__float_as_uint(a0)), "r"(__float_as_uint(a1)),
          "r"(__float_as_uint(a2)), "r"(__float_as_uint(a3)),
          "r"(__float_as_uint(b0)), "r"(__float_as_uint(b1)));
}

// bf16 m16n8k16 (QK)
__device__ __forceinline__ void mma16bf(float c[4], const uint32_t a[4],
                                        uint32_t b0, uint32_t b1) {
    asm volatile(
        "mma.sync.aligned.m16n8k16.row.col.f32.bf16.bf16.f32 "
        "{%0,%1,%2,%3}, {%4,%5,%6,%7}, {%8,%9}, {%0,%1,%2,%3};"
        : "+f"(c[0]), "+f"(c[1]), "+f"(c[2]), "+f"(c[3])
        : "r"(a[0]), "r"(a[1]), "r"(a[2]), "r"(a[3]), "r"(b0), "r"(b1));
}

// pack two floats' bf16 hi-parts and residual lo-parts
__device__ __forceinline__ void bf_split2(float x0, float x1,
                                          uint32_t& hp, uint32_t& lp) {
    __nv_bfloat16 h0 = __float2bfloat16(x0);
    __nv_bfloat16 h1 = __float2bfloat16(x1);
    float l0 = x0 - __bfloat162float(h0);
    float l1 = x1 - __bfloat162float(h1);
    hp = ((uint32_t)__bfloat16_as_ushort(h1) << 16) | __bfloat16_as_ushort(h0);
    lp = ((uint32_t)__bfloat16_as_ushort(__float2bfloat16(l1)) << 16)
       | __bfloat16_as_ushort(__float2bfloat16(l0));
}

__global__ __launch_bounds__(256, 1)
void attn_fwd_kernel(const float* __restrict__ Qg, const float* __restrict__ Kg,
                     const float* __restrict__ Vg, float* __restrict__ Og,
                     float* __restrict__ Wg)
{
    extern __shared__ unsigned char smb[];
    uint32_t* Kw  = (uint32_t*)(smb + SM_KIV);  // interleaved {hi,lo} words
    const uint2* Kiv2 = (const uint2*)(smb + SM_KIV);
    float*    Vsm = (float*)(smb + SM_V);       // 2 buffers of [128][VST2]
    float*    Ps  = (float*)(smb + SM_P);

    const int tid  = threadIdx.x;
    const int wid  = tid >> 5;
    const int lane = tid & 31;
    const int g    = lane >> 2;     // 0..7
    const int t    = lane & 3;      // 0..3

    const int qt = 15 - (int)blockIdx.x;  // heavy tiles first
    const int bh = blockIdx.y;
    const int q0 = qt * QT;
    const int nch = qt + 1;
    const size_t base = (size_t)bh * SQ * DD;

    const int row0 = wid * 16 + g;
    const int row1 = row0 + 8;
    const int qg0  = q0 + row0;
    const int qg1  = q0 + row1;

    // staging decode
    const int sK_dg = tid & 7, sK_r = tid >> 3;            // K: 32 rows/iter
    const int sV_key = tid >> 4, sV_d = (tid & 15) << 2;   // V: 16 keys/iter
    const uint32_t vbase_u32 = smem_u32(Vsm);
    const uint32_t vdst_off  = (uint32_t)(sV_key * VST2 + sV_d) * 4;

    // ---- cp.async V chunk 0 into buffer 0 ----
    {
        const float* vp = Vg + base + (size_t)sV_key * DD + sV_d;
        #pragma unroll
        for (int it = 0; it < 8; it++)
            CP_ASYNC16(vbase_u32 + vdst_off + (uint32_t)(it * 16 * VST2 * 4),
                       vp + (size_t)(it * 16) * DD);
        CP_COMMIT();
    }

    // ---- prefetch K chunk 0 into registers (bf16 split) ----
    uint4 pkh[4], pkl[4];
    {
        const float* kp = Kg + base + (size_t)sK_r * DD + sK_dg * 8;
        #pragma unroll
        for (int it = 0; it < 4; it++) {
            float4 k0 = *(const float4*)(kp + (size_t)(it * 32) * DD);
            float4 k1 = *(const float4*)(kp + (size_t)(it * 32) * DD + 4);
            bf_split2(k0.x, k0.y, pkh[it].x, pkl[it].x);
            bf_split2(k0.z, k0.w, pkh[it].y, pkl[it].y);
            bf_split2(k1.x, k1.y, pkh[it].z, pkl[it].z);
            bf_split2(k1.z, k1.w, pkh[it].w, pkl[it].w);
        }
    }

    // ---- stage raw Q into P area, build bf16 hi/lo A-frags (persist) ----
    for (int i4 = tid; i4 < QT * DD / 4; i4 += 256) {
        int r = i4 >> 4, c = (i4 & 15) << 2;
        float4 v = *(const float4*)(Qg + base + (size_t)(q0 + r) * DD + c);
        *(float4*)&Ps[r * PST + c] = v;
    }
    __syncthreads();

    uint32_t qh[4][4], ql[4][4];
    #pragma unroll
    for (int k16 = 0; k16 < 4; k16++) {
        float2 qa = *(const float2*)&Ps[row0 * PST + k16 * 16 + 2 * t];
        float2 qb = *(const float2*)&Ps[row1 * PST + k16 * 16 + 2 * t];
        float2 qc = *(const float2*)&Ps[row0 * PST + k16 * 16 + 2 * t + 8];
        float2 qd = *(const float2*)&Ps[row1 * PST + k16 * 16 + 2 * t + 8];
        bf_split2(qa.x, qa.y, qh[k16][0], ql[k16][0]);
        bf_split2(qb.x, qb.y, qh[k16][1], ql[k16][1]);
        bf_split2(qc.x, qc.y, qh[k16][2], ql[k16][2]);
        bf_split2(qd.x, qd.y, qh[k16][3], ql[k16][3]);
    }

    float o[8][4];
    #pragma unroll
    for (int n = 0; n < 8; n++)
        #pragma unroll
        for (int j = 0; j < 4; j++) o[n][j] = 0.f;
    float psum0 = 0.f, psum1 = 0.f;

    for (int ch = 0; ch < nch; ch++) {
        const int kb = ch * CH;
        float* Vb = Vsm + (ch & 1) * (VBUF_B / 4);
        __syncthreads();   // previous chunk compute done

        // ---- STS prefetched K (interleaved {hi,lo} per d-pair) ----
        {
            // uint2 element base for this thread's 8 d-values (4 pairs + 4 pairs)
            const int e0 = sK_r * KIST + (sK_dg >> 1) * 8 + (sK_dg & 1) * 4;
            #pragma unroll
            for (int it = 0; it < 4; it++) {
                const int w0 = (e0 + it * 32 * KIST) * 2;   // word index
                uint4 a = make_uint4(pkh[it].x, pkl[it].x, pkh[it].y, pkl[it].y);
                uint4 b = make_uint4(pkh[it].z, pkl[it].z, pkh[it].w, pkl[it].w);
                *(uint4*)&Kw[w0]     = a;
                *(uint4*)&Kw[w0 + 4] = b;
            }
        }
        // ---- cp.async next V chunk into the other buffer ----
        if (ch + 1 < nch) {
            const uint32_t dst = vbase_u32 + (uint32_t)(((ch + 1) & 1) * VBUF_B)
                               + vdst_off;
            const float* vp = Vg + base + (size_t)(kb + CH + sV_key) * DD + sV_d;
            #pragma unroll
            for (int it = 0; it < 8; it++)
                CP_ASYNC16(dst + (uint32_t)(it * 16 * VST2 * 4),
                           vp + (size_t)(it * 16) * DD);
            CP_COMMIT();
            CP_WAIT(1);    // this chunk's V group arrived
        } else {
            CP_WAIT(0);
        }
        __syncthreads();   // K STS + V arrivals visible

        // ---- round this chunk's V to tf32 in place (accuracy margin) ----
        {
            float* vq = Vb + sV_key * VST2 + sV_d;
            #pragma unroll
            for (int it = 0; it < 8; it++) {
                float4 v = *(const float4*)(vq + it * 16 * VST2);
                v.x = to_tf32(v.x); v.y = to_tf32(v.y);
                v.z = to_tf32(v.z); v.w = to_tf32(v.w);
                *(float4*)(vq + it * 16 * VST2) = v;
            }
        }
        __syncthreads();

        const bool diag = (ch == qt);

        #pragma unroll
        for (int h = 0; h < 2; h++) {
            // ---- S half: 3x bf16 MMA (hh + lh + hl), LDS.64 K frags ----
            float s[8][4];
            #pragma unroll
            for (int n = 0; n < 8; n++)
                #pragma unroll
                for (int j = 0; j < 4; j++) s[n][j] = 0.f;

            #pragma unroll
            for (int k16 = 0; k16 < 4; k16++) {
                #pragma unroll
                for (int nt = 0; nt < 8; nt++) {
                    const int e = (h * 64 + nt * 8 + g) * KIST + k16 * 8 + t;
                    uint2 c0 = Kiv2[e];        // {b0h, b0l}
                    uint2 c1 = Kiv2[e + 4];    // {b1h, b1l}
                    mma16bf(s[nt], qh[k16], c0.x, c1.x);
                    mma16bf(s[nt], ql[k16], c0.x, c1.x);
                    mma16bf(s[nt], qh[k16], c0.y, c1.y);
                }
            }

            // ---- prefetch next K (after QK so LDGs don't delay QK LDS) ----
            if (h == 0 && ch + 1 < nch) {
                const float* kp = Kg + base + (size_t)(kb + CH + sK_r) * DD
                                + sK_dg * 8;
                #pragma unroll
                for (int it = 0; it < 4; it++) {
                    float4 k0 = *(const float4*)(kp + (size_t)(it * 32) * DD);
                    float4 k1 = *(const float4*)(kp + (size_t)(it * 32) * DD + 4);
                    bf_split2(k0.x, k0.y, pkh[it].x, pkl[it].x);
                    bf_split2(k0.z, k0.w, pkh[it].y, pkl[it].y);
                    bf_split2(k1.x, k1.y, pkh[it].z, pkl[it].z);
                    bf_split2(k1.z, k1.w, pkh[it].w, pkl[it].w);
                }
            }

            // ---- exp, mask, psum, P -> smem (raw fp32) ----
            #pragma unroll
            for (int nt = 0; nt < 8; nt++) {
                const int col = kb + h * 64 + nt * 8 + 2 * t;
                float p00 = __expf(s[nt][0] * SCALE);
                float p01 = __expf(s[nt][1] * SCALE);
                float p10 = __expf(s[nt][2] * SCALE);
                float p11 = __expf(s[nt][3] * SCALE);
                if (diag) {
                    if (col     > qg0) p00 = 0.f;
                    if (col + 1 > qg0) p01 = 0.f;
                    if (col     > qg1) p10 = 0.f;
                    if (col + 1 > qg1) p11 = 0.f;
                }
                psum0 += p00 + p01;
                psum1 += p10 + p11;
                *(float2*)&Ps[row0 * PST + nt * 8 + 2 * t] = make_float2(p00, p01);
                *(float2*)&Ps[row1 * PST + nt * 8 + 2 * t] = make_float2(p10, p11);
            }
            __syncwarp();   // P rows are warp-private

            // ---- O += P_half @ V_half (tf32; V pre-rounded) ----
            #pragma unroll
            for (int k = 0; k < 8; k++) {
                float a0 = Ps[row0 * PST + 8 * k + t];
                float a1 = Ps[row1 * PST + 8 * k + t];
                float a2 = Ps[row0 * PST + 8 * k + t + 4];
                float a3 = Ps[row1 * PST + 8 * k + t + 4];
                const float* vr0 = Vb + (h * 64 + 8 * k + t) * VST2;
                const float* vr1 = vr0 + 4 * VST2;
                #pragma unroll
                for (int nt = 0; nt < 8; nt++) {
                    const int d = nt * 8 + g;
                    mma8(o[nt], a0, a1, a2, a3, vr0[d], vr1[d]);
                }
            }

            // ---- W store: coalesced STG.128 from this warp's P rows ----
            {
                const int wr2 = lane >> 4;       // 0/1
                const int c4  = (lane & 15) << 2;
                float* wb = Wg + ((size_t)bh * SQ + q0) * SQ + kb + h * 64 + c4;
                #pragma unroll
                for (int st = 0; st < 8; st++) {
                    const int r = wid * 16 + st * 2 + wr2;
                    float4 v = *(const float4*)&Ps[r * PST + c4];
                    *(float4*)(wb + (size_t)r * SQ) = v;
                }
            }
            __syncwarp();   // Ps reused by next half
        }
    }

    // ---- rowsum reduce across the 4 quad lanes -> 1/l ----
    psum0 += __shfl_xor_sync(0xffffffffu, psum0, 1);
    psum0 += __shfl_xor_sync(0xffffffffu, psum0, 2);
    psum1 += __shfl_xor_sync(0xffffffffu, psum1, 1);
    psum1 += __shfl_xor_sync(0xffffffffu, psum1, 2);
    const float inv0 = 1.0f / psum0;
    const float inv1 = 1.0f / psum1;
    if (t == 0) {
        g_Linv[bh * SQ + qg0] = inv0;
        g_Linv[bh * SQ + qg1] = inv1;
    }

    // ---- O = acc * inv -> global ----
    #pragma unroll
    for (int nt = 0; nt < 8; nt++) {
        const int col = nt * 8 + 2 * t;
        *(float2*)(Og + base + (size_t)qg0 * DD + col) =
            make_float2(o[nt][0] * inv0, o[nt][1] * inv0);
        *(float2*)(Og + base + (size_t)qg1 * DD + col) =
            make_float2(o[nt][2] * inv1, o[nt][3] * inv1);
    }
}

// Kernel 2 (validated: ~120-125us @ DRAM roofline): normalize causal region by
// 1/rowsum, zero-fill the never-written upper region.
__global__ void norm_weights_kernel(float* __restrict__ W)
{
    const size_t total4 = (size_t)NBH * SQ * (SQ / 4);
    size_t idx = (size_t)blockIdx.x * blockDim.x + threadIdx.x;
    if (idx >= total4) return;
    const int row = (int)(idx >> 9);          // bh*SQ + q  (512 float4 per row)
    const int c4  = (int)(idx & 511);
    const int q   = row & (SQ - 1);
    const int k0  = c4 << 2;
    const int boundary = ((q >> 7) + 1) << 7; // kernel 1 wrote k < boundary
    float4* W4 = (float4*)W;
    if (k0 >= boundary) {
        W4[idx] = make_float4(0.f, 0.f, 0.f, 0.f);
    } else {
        const float m = g_Linv[row];
        float4 v = W4[idx];
        v.x *= m; v.y *= m; v.z *= m; v.w *= m;
        W4[idx] = v;
    }
}

extern "C" void kernel_launch(void* const* d_in, const int* in_sizes, int n_in,
                              void* d_out, int out_size)
{
    const float* Q = (const float*)d_in[0];
    const float* K = (const float*)d_in[1];
    const float* V = (const float*)d_in[2];
    // d_in[3]: causal mask — implemented analytically.

    float* out = (float*)d_out;
    const long long outN = (long long)NBH * SQ * DD;          //   4,194,304
    const long long wN   = (long long)NBH * SQ * SQ;          // 134,217,728
    float* W = ((long long)out_size >= outN + wN) ? (out + outN) : (float*)0;

    cudaFuncSetAttribute(attn_fwd_kernel,
                         cudaFuncAttributeMaxDynamicSharedMemorySize, SMEM_BYTES);

    dim3 grid(SQ / QT, NBH);
    attn_fwd_kernel<<<grid, 256, SMEM_BYTES>>>(Q, K, V, out, W);

    if (W) {
        const unsigned total4 = (unsigned)(wN / 4);
        norm_weights_kernel<<<(total4 + 255) / 256, 256>>>(W);
    }
}